// round 1
// baseline (speedup 1.0000x reference)
#include <cuda_runtime.h>

// CHIVE clockwork RNN scan.
// T=2048 timesteps (serial), B=2048 batch (parallel), H=32.
// One warp per batch element; lane = hidden index j.
// State in shared (broadcast LDS.128); hot weights in per-lane registers.

#define TT 2048
#define BB 2048
#define HH 32
#define DF 8
#define DS 24
#define NW 8                 // warps per block
#define NTHREADS (NW * 32)

__device__ __forceinline__ float fast_tanh(float x) {
    // tanh(x) = 1 - 2/(exp(2x)+1); MUFU.EX2 + MUFU.RCP based, err ~1e-6.
    float e = __expf(2.0f * x);
    return 1.0f - __fdividef(2.0f, e + 1.0f);
}

__global__ __launch_bounds__(NTHREADS)
void chive_kernel(const float* __restrict__ frnn,
                  const float* __restrict__ phrnn,
                  const float* __restrict__ syl,
                  const float* __restrict__ Wxf, const float* __restrict__ Whf,
                  const float* __restrict__ bfv,
                  const float* __restrict__ Wxp, const float* __restrict__ Whp,
                  const float* __restrict__ bpv,
                  const float* __restrict__ Wxs, const float* __restrict__ Whs,
                  const float* __restrict__ bsv,
                  const int* __restrict__ fclk, const int* __restrict__ pclk,
                  const int* __restrict__ sfreq,
                  float* __restrict__ out)
{
    __shared__ float sWhf[HH * HH];
    __shared__ float sWhp[HH * HH];
    __shared__ unsigned char sflags[TT];
    __shared__ __align__(16) float sh[NW][5][HH];   // hf, hp, hs0, hs1, hs2
    __shared__ __align__(16) float sxs[NW][HH];

    const int tid  = threadIdx.x;
    const int w    = tid >> 5;
    const int lane = tid & 31;
    const int b    = blockIdx.x * NW + w;

    // --- block-wide init ---
    for (int i = tid; i < HH * HH; i += NTHREADS) {
        sWhf[i] = Whf[i];
        sWhp[i] = Whp[i];
    }
    for (int t = tid; t < TT; t += NTHREADS) {
        int uf = ((t % (fclk[t] + 1)) == 0) ? 1 : 0;
        int up = ((t % (pclk[t] + 1)) == 0) ? 2 : 0;
        int us = (sfreq[t] == 1) ? 4 : 0;
        sflags[t] = (unsigned char)(uf | up | us);
    }
    for (int i = tid; i < NW * 5 * HH; i += NTHREADS)
        ((float*)sh)[i] = 0.0f;
    __syncthreads();

    // --- per-lane weight columns (registers) ---
    float whs_r[HH], wxs_r[HH], wxf_r[DF], wxp_r[DF];
#pragma unroll
    for (int k = 0; k < HH; k++) {
        whs_r[k] = Whs[k * HH + lane];
        wxs_r[k] = Wxs[k * HH + lane];
    }
#pragma unroll
    for (int k = 0; k < DF; k++) {
        wxf_r[k] = Wxf[k * HH + lane];
        wxp_r[k] = Wxp[k * HH + lane];
    }
    const float bf = bfv[lane];
    const float bp = bpv[lane];
    const float bs = bsv[lane];

    // cached projections z0 = h_f @ Wx_s, z1 = h_p @ Wx_s (valid while h_f/h_p frozen)
    float z0 = 0.0f, z1 = 0.0f;

    const float4* hf4 = (const float4*)sh[w][0];
    const float4* hp4 = (const float4*)sh[w][1];
    const float4* s04 = (const float4*)sh[w][2];
    const float4* s14 = (const float4*)sh[w][3];
    const float4* s24 = (const float4*)sh[w][4];
    const float4* xs4 = (const float4*)sxs[w];

    for (int t = 0; t < TT; t++) {
        const int fl = sflags[t];
        if (!fl) continue;                       // uniform per block: no divergence
        const size_t tb = (size_t)t * BB + b;

        // ---------------- f cell ----------------
        if (fl & 1) {
            const float4* xg = (const float4*)(frnn + tb * DF);
            float4 xa = xg[0];
            float4 xb = xg[1];
            float a0 = bf, a1 = 0.f;
#pragma unroll
            for (int q = 0; q < 8; q++) {
                float4 h4 = hf4[q];
                a0 = fmaf(h4.x, sWhf[(4 * q + 0) * HH + lane], a0);
                a1 = fmaf(h4.y, sWhf[(4 * q + 1) * HH + lane], a1);
                a0 = fmaf(h4.z, sWhf[(4 * q + 2) * HH + lane], a0);
                a1 = fmaf(h4.w, sWhf[(4 * q + 3) * HH + lane], a1);
            }
            a0 = fmaf(xa.x, wxf_r[0], a0); a1 = fmaf(xa.y, wxf_r[1], a1);
            a0 = fmaf(xa.z, wxf_r[2], a0); a1 = fmaf(xa.w, wxf_r[3], a1);
            a0 = fmaf(xb.x, wxf_r[4], a0); a1 = fmaf(xb.y, wxf_r[5], a1);
            a0 = fmaf(xb.z, wxf_r[6], a0); a1 = fmaf(xb.w, wxf_r[7], a1);
            float hn = fast_tanh(a0 + a1);
            __syncwarp();                        // all lanes done reading old h_f
            sh[w][0][lane] = hn;
            __syncwarp();                        // new h_f visible warp-wide
            // refresh z0 = h_f @ Wx_s
            float c0 = 0.f, c1 = 0.f;
#pragma unroll
            for (int q = 0; q < 8; q++) {
                float4 h4 = hf4[q];
                c0 = fmaf(h4.x, wxs_r[4 * q + 0], c0);
                c1 = fmaf(h4.y, wxs_r[4 * q + 1], c1);
                c0 = fmaf(h4.z, wxs_r[4 * q + 2], c0);
                c1 = fmaf(h4.w, wxs_r[4 * q + 3], c1);
            }
            z0 = c0 + c1;
        }

        // ---------------- p cell ----------------
        if (fl & 2) {
            const float4* xg = (const float4*)(phrnn + tb * DF);
            float4 xa = xg[0];
            float4 xb = xg[1];
            float a0 = bp, a1 = 0.f;
#pragma unroll
            for (int q = 0; q < 8; q++) {
                float4 h4 = hp4[q];
                a0 = fmaf(h4.x, sWhp[(4 * q + 0) * HH + lane], a0);
                a1 = fmaf(h4.y, sWhp[(4 * q + 1) * HH + lane], a1);
                a0 = fmaf(h4.z, sWhp[(4 * q + 2) * HH + lane], a0);
                a1 = fmaf(h4.w, sWhp[(4 * q + 3) * HH + lane], a1);
            }
            a0 = fmaf(xa.x, wxp_r[0], a0); a1 = fmaf(xa.y, wxp_r[1], a1);
            a0 = fmaf(xa.z, wxp_r[2], a0); a1 = fmaf(xa.w, wxp_r[3], a1);
            a0 = fmaf(xb.x, wxp_r[4], a0); a1 = fmaf(xb.y, wxp_r[5], a1);
            a0 = fmaf(xb.z, wxp_r[6], a0); a1 = fmaf(xb.w, wxp_r[7], a1);
            float hn = fast_tanh(a0 + a1);
            __syncwarp();
            sh[w][1][lane] = hn;
            __syncwarp();
            float c0 = 0.f, c1 = 0.f;
#pragma unroll
            for (int q = 0; q < 8; q++) {
                float4 h4 = hp4[q];
                c0 = fmaf(h4.x, wxs_r[4 * q + 0], c0);
                c1 = fmaf(h4.y, wxs_r[4 * q + 1], c1);
                c0 = fmaf(h4.z, wxs_r[4 * q + 2], c0);
                c1 = fmaf(h4.w, wxs_r[4 * q + 3], c1);
            }
            z1 = c0 + c1;
        }

        // ---------------- syl cell (3 slabs) ----------------
        if (fl & 4) {
            // issue gmem load early; consume after the 96-FMA Wh block
            float xsv = (lane < DS) ? syl[tb * DS + lane] : 0.0f;

            float p0 = bs + z0, q0 = 0.f;
            float p1 = bs + z1, q1 = 0.f;
            float p2 = bs,      q2 = 0.f;
#pragma unroll
            for (int qq = 0; qq < 8; qq++) {
                float wr0 = whs_r[4 * qq + 0];
                float wr1 = whs_r[4 * qq + 1];
                float wr2 = whs_r[4 * qq + 2];
                float wr3 = whs_r[4 * qq + 3];
                float4 a4 = s04[qq];
                p0 = fmaf(a4.x, wr0, p0); q0 = fmaf(a4.y, wr1, q0);
                p0 = fmaf(a4.z, wr2, p0); q0 = fmaf(a4.w, wr3, q0);
                float4 b4 = s14[qq];
                p1 = fmaf(b4.x, wr0, p1); q1 = fmaf(b4.y, wr1, q1);
                p1 = fmaf(b4.z, wr2, p1); q1 = fmaf(b4.w, wr3, q1);
                float4 c4 = s24[qq];
                p2 = fmaf(c4.x, wr0, p2); q2 = fmaf(c4.y, wr1, q2);
                p2 = fmaf(c4.z, wr2, p2); q2 = fmaf(c4.w, wr3, q2);
            }
            __syncwarp();                        // prior sxs readers done
            sxs[w][lane] = xsv;
            __syncwarp();                        // xsv visible warp-wide
#pragma unroll
            for (int qq = 0; qq < 6; qq++) {     // only first 24 cols (zero-padded)
                float4 x4 = xs4[qq];
                p2 = fmaf(x4.x, wxs_r[4 * qq + 0], p2);
                q2 = fmaf(x4.y, wxs_r[4 * qq + 1], q2);
                p2 = fmaf(x4.z, wxs_r[4 * qq + 2], p2);
                q2 = fmaf(x4.w, wxs_r[4 * qq + 3], q2);
            }
            float n0 = fast_tanh(p0 + q0);
            float n1 = fast_tanh(p1 + q1);
            float n2 = fast_tanh(p2 + q2);
            sh[w][2][lane] = n0;
            sh[w][3][lane] = n1;
            sh[w][4][lane] = n2;
            __syncwarp();
        }
    }

    // output: h_s [3, B, H]
    out[0 * BB * HH + b * HH + lane] = sh[w][2][lane];
    out[1 * BB * HH + b * HH + lane] = sh[w][3][lane];
    out[2 * BB * HH + b * HH + lane] = sh[w][4][lane];
}

extern "C" void kernel_launch(void* const* d_in, const int* in_sizes, int n_in,
                              void* d_out, int out_size) {
    const float* frnn  = (const float*)d_in[0];
    const float* phrnn = (const float*)d_in[1];
    const float* syl   = (const float*)d_in[2];
    const float* Wxf   = (const float*)d_in[3];
    const float* Whf   = (const float*)d_in[4];
    const float* bfv   = (const float*)d_in[5];
    const float* Wxp   = (const float*)d_in[6];
    const float* Whp   = (const float*)d_in[7];
    const float* bpv   = (const float*)d_in[8];
    const float* Wxs   = (const float*)d_in[9];
    const float* Whs   = (const float*)d_in[10];
    const float* bsv   = (const float*)d_in[11];
    const int*   fclk  = (const int*)d_in[12];
    const int*   pclk  = (const int*)d_in[13];
    const int*   sfreq = (const int*)d_in[14];
    float* out = (float*)d_out;

    dim3 grid(BB / NW);   // 256 CTAs x 8 warps = 2048 warps (one per batch row)
    dim3 block(NTHREADS);
    chive_kernel<<<grid, block>>>(frnn, phrnn, syl,
                                  Wxf, Whf, bfv,
                                  Wxp, Whp, bpv,
                                  Wxs, Whs, bsv,
                                  fclk, pclk, sfreq, out);
}